// round 14
// baseline (speedup 1.0000x reference)
#include <cuda_runtime.h>
#include <cuda_bf16.h>
#include <math.h>
#include <stdint.h>

// ---------------------------------------------------------------------------
// CosmopsychiaPINN via forward-mode Taylor propagation.
// Hidden layers: warp-level bf16 mma.sync (m16n8k16) split-GEMM, 3 passes:
//   C = Ahi*Whi + Ahi*Wlo + Alo*Whi   (fp32 accumulate)
// R14: 512-thread CTAs, warp tile 32x32 (16 warps/CTA) -> 32 warps/SM,
// regs<=64, same CTA tile + per-accumulator MMA order as R12 (bit-identical).
// Redundant bottom __syncthreads removed.
// Layer GEMM: M=8*B=65536, N=512, K=512.  (tcgen05 unusable: sm_100 target.)
// ---------------------------------------------------------------------------

#define HDIM 512
#define NVEC 8
#define MAXB 8192
#define TM   64
#define TN   256
#define KCH  32
#define PLANE ((size_t)NVEC * MAXB * HDIM)

#define ROWP 40
#define A_PLANE_BYTES (TM * ROWP * 2)     // 5120
#define B_PLANE_BYTES (TN * ROWP * 2)     // 20480
#define STAGE_BYTES (2 * A_PLANE_BYTES + 2 * B_PLANE_BYTES)  // 51200
#define SMEM_TOTAL (2 * STAGE_BYTES)                          // 102400

__device__ __nv_bfloat16 g_Ahi[2][PLANE];
__device__ __nv_bfloat16 g_Alo[2][PLANE];
__device__ __nv_bfloat16 g_Wth[6 * HDIM * HDIM];
__device__ __nv_bfloat16 g_Wtl[6 * HDIM * HDIM];

__device__ __forceinline__ uint32_t smem_u32(const void* p) {
    uint32_t a;
    asm("{ .reg .u64 t; cvta.to.shared.u64 t, %1; cvt.u32.u64 %0, t; }"
        : "=r"(a) : "l"(p));
    return a;
}
__device__ __forceinline__ void cp16(uint32_t dst, const void* src) {
    asm volatile("cp.async.cg.shared.global [%0], [%1], 16;"
                 :: "r"(dst), "l"(src) : "memory");
}
__device__ __forceinline__ void ldmx4(uint32_t* r, uint32_t addr) {
    asm volatile("ldmatrix.sync.aligned.m8n8.x4.shared.b16 {%0,%1,%2,%3}, [%4];"
                 : "=r"(r[0]), "=r"(r[1]), "=r"(r[2]), "=r"(r[3]) : "r"(addr));
}
__device__ __forceinline__ void mma16816(float* c, const uint32_t* a,
                                         const uint32_t* b) {
    asm volatile(
        "mma.sync.aligned.m16n8k16.row.col.f32.bf16.bf16.f32 "
        "{%0,%1,%2,%3}, {%4,%5,%6,%7}, {%8,%9}, {%0,%1,%2,%3};"
        : "+f"(c[0]), "+f"(c[1]), "+f"(c[2]), "+f"(c[3])
        : "r"(a[0]), "r"(a[1]), "r"(a[2]), "r"(a[3]), "r"(b[0]), "r"(b[1]));
}
__device__ __forceinline__ void bf16_split(float f, __nv_bfloat16& hi,
                                           __nv_bfloat16& lo) {
    hi = __float2bfloat16(f);
    lo = __float2bfloat16(f - __bfloat162float(hi));
}

// ---------------------------------------------------------------------------
__global__ void prep_w_kernel(const float* __restrict__ Wh,
                              __nv_bfloat16* __restrict__ Wth,
                              __nv_bfloat16* __restrict__ Wtl)
{
    int idx = blockIdx.x * blockDim.x + threadIdx.x;
    if (idx >= 6 * HDIM * HDIM) return;
    int l = idx >> 18;
    int rem = idx & (HDIM * HDIM - 1);
    int n = rem >> 9;
    int k = rem & (HDIM - 1);
    float w = Wh[(size_t)l * HDIM * HDIM + (size_t)k * HDIM + n];
    __nv_bfloat16 hi, lo;
    bf16_split(w, hi, lo);
    Wth[idx] = hi;
    Wtl[idx] = lo;
}

// ---------------------------------------------------------------------------
__global__ void init_kernel(const float* __restrict__ x,
                            const float* __restrict__ W0,
                            const float* __restrict__ b0,
                            __nv_bfloat16* __restrict__ Shi,
                            __nv_bfloat16* __restrict__ Slo, int Bn)
{
    int idx = blockIdx.x * blockDim.x + threadIdx.x;
    if (idx >= Bn * HDIM) return;
    int s = idx >> 9;
    int j = idx & (HDIM - 1);

    float x0 = x[s * 4 + 0], x1 = x[s * 4 + 1];
    float x2 = x[s * 4 + 2], x3 = x[s * 4 + 3];
    float w0 = W0[0 * HDIM + j];
    float w1 = W0[1 * HDIM + j];
    float w2 = W0[2 * HDIM + j];
    float w3 = W0[3 * HDIM + j];

    float z = fmaf(x0, w0, fmaf(x1, w1, fmaf(x2, w2, fmaf(x3, w3, b0[j]))));
    float h = tanhf(z);
    float g = 1.f - h * h;

    float vals[8];
    vals[0] = h;
    vals[1] = g * w0;
    vals[2] = g * w1;
    vals[3] = g * w2;
    vals[4] = g * w3;
    vals[5] = -2.f * h * g * w0 * w0;
    vals[6] = -2.f * h * g * w1 * w1;
    vals[7] = -2.f * h * g * w2 * w2;

#pragma unroll
    for (int v = 0; v < 8; v++) {
        size_t off = (size_t)(s * 8 + v) * HDIM + j;
        __nv_bfloat16 hi, lo;
        bf16_split(vals[v], hi, lo);
        Shi[off] = hi;
        Slo[off] = lo;
    }
}

// ---------------------------------------------------------------------------
// Hidden layer: bf16 mma.sync 3-pass GEMM, cp.async double-buffered k-loop.
// Grid (HDIM/TN=2, Mtot/TM=1024), 512 threads = 16 warps (2m x 8n),
// warp tile 32x32. Stage: Ahi|Alo (64x40 bf16) + Bhi|Blo (256x40 bf16).
// ---------------------------------------------------------------------------
__global__ void __launch_bounds__(512, 2)
layer_mma_kernel(const __nv_bfloat16* __restrict__ Ahi,
                 const __nv_bfloat16* __restrict__ Alo,
                 const __nv_bfloat16* __restrict__ Bhi,
                 const __nv_bfloat16* __restrict__ Blo,
                 const float* __restrict__ bias,
                 __nv_bfloat16* __restrict__ Ohi,
                 __nv_bfloat16* __restrict__ Olo)
{
    extern __shared__ char sm[];

    int t = threadIdx.x;
    int lane = t & 31;
    int wid = t >> 5;
    int warpM = wid >> 3;       // 0..1
    int warpN = wid & 7;        // 0..7
    int mbase = blockIdx.y * TM;
    int nbase = blockIdx.x * TN;

    // Loader geometry: A tile 256 float4s (threads 0-255, 1 each);
    // B tile 1024 float4s (2 per thread).
    int aRow = (t & 255) >> 2, aKq = t & 3;
    uint32_t aSo = aRow * (ROWP * 2) + aKq * 16;
    size_t aGo = (size_t)(mbase + aRow) * HDIM + aKq * 8;
    int aAct = (t < 256);

    uint32_t bSo[2];
    size_t bGo[2];
#pragma unroll
    for (int j = 0; j < 2; j++) {
        int i = t + 512 * j;
        int row = i >> 2, kq = i & 3;
        bSo[j] = row * (ROWP * 2) + kq * 16;
        bGo[j] = (size_t)(nbase + row) * HDIM + kq * 8;
    }

    uint32_t stageAddr[2];
    stageAddr[0] = smem_u32(sm);
    stageAddr[1] = stageAddr[0] + STAGE_BYTES;

    // ldmatrix lane-dependent byte offsets.
    uint32_t aoff[2];
#pragma unroll
    for (int fm = 0; fm < 2; fm++)
        aoff[fm] = ((warpM * 32 + fm * 16 + (lane & 15)) * ROWP +
                    ((lane >> 4) & 1) * 8) * 2;
    uint32_t boff[2];
#pragma unroll
    for (int p = 0; p < 2; p++)
        boff[p] = ((warpN * 32 + p * 16 + (lane & 7) + ((lane >> 4) & 1) * 8)
                   * ROWP + ((lane >> 3) & 1) * 8) * 2;

    float c[2][4][4];
#pragma unroll
    for (int fm = 0; fm < 2; fm++)
#pragma unroll
        for (int f = 0; f < 4; f++)
#pragma unroll
            for (int r = 0; r < 4; r++) c[fm][f][r] = 0.f;

    // ---- prefetch chunk 0 into stage 0 ----
    {
        uint32_t sb = stageAddr[0];
        if (aAct) {
            cp16(sb + aSo, Ahi + aGo);
            cp16(sb + A_PLANE_BYTES + aSo, Alo + aGo);
        }
#pragma unroll
        for (int j = 0; j < 2; j++) {
            cp16(sb + 2 * A_PLANE_BYTES + bSo[j], Bhi + bGo[j]);
            cp16(sb + 2 * A_PLANE_BYTES + B_PLANE_BYTES + bSo[j], Blo + bGo[j]);
        }
        asm volatile("cp.async.commit_group;" ::: "memory");
    }

    const int NKCH = HDIM / KCH;   // 16
    for (int kc = 0; kc < NKCH; kc++) {
        int cur = kc & 1;
        asm volatile("cp.async.wait_group 0;" ::: "memory");
        __syncthreads();   // also orders: all warps done reading stage cur^1

        if (kc + 1 < NKCH) {
            uint32_t sb = stageAddr[cur ^ 1];
            size_t kofe = (size_t)(kc + 1) * KCH;
            if (aAct) {
                cp16(sb + aSo, Ahi + aGo + kofe);
                cp16(sb + A_PLANE_BYTES + aSo, Alo + aGo + kofe);
            }
#pragma unroll
            for (int j = 0; j < 2; j++) {
                cp16(sb + 2 * A_PLANE_BYTES + bSo[j], Bhi + bGo[j] + kofe);
                cp16(sb + 2 * A_PLANE_BYTES + B_PLANE_BYTES + bSo[j],
                     Blo + bGo[j] + kofe);
            }
            asm volatile("cp.async.commit_group;" ::: "memory");
        }

        uint32_t aBaseH = stageAddr[cur];
        uint32_t aBaseL = aBaseH + A_PLANE_BYTES;
        uint32_t bBaseH = aBaseH + 2 * A_PLANE_BYTES;
        uint32_t bBaseL = bBaseH + B_PLANE_BYTES;

#pragma unroll
        for (int kh = 0; kh < 2; kh++) {
            uint32_t kb2 = kh * 32;
            uint32_t ah[2][4], al[2][4];
#pragma unroll
            for (int fm = 0; fm < 2; fm++) {
                ldmx4(ah[fm], aBaseH + aoff[fm] + kb2);
                ldmx4(al[fm], aBaseL + aoff[fm] + kb2);
            }
#pragma unroll
            for (int p = 0; p < 2; p++) {
                uint32_t bh[4], bl[4];
                ldmx4(bh, bBaseH + boff[p] + kb2);
                ldmx4(bl, bBaseL + boff[p] + kb2);
#pragma unroll
                for (int fm = 0; fm < 2; fm++)
#pragma unroll
                    for (int q = 0; q < 2; q++) {
                        int f = 2 * p + q;
                        mma16816(c[fm][f], ah[fm], bh + 2 * q);
                        mma16816(c[fm][f], ah[fm], bl + 2 * q);
                        mma16816(c[fm][f], al[fm], bh + 2 * q);
                    }
            }
        }
        // (no bottom sync: top-of-loop sync of the next iteration orders
        //  all readers of this stage before it is overwritten)
    }

    // ---- epilogue: tanh-chain via warp shuffles, bf16 hi/lo stores ----
    int v = lane >> 2;
    int dl = (((v >= 5) ? (v - 4) : 0) << 2) | (lane & 3);
#pragma unroll
    for (int fm = 0; fm < 2; fm++) {
        int gr0 = mbase + warpM * 32 + fm * 16 + (lane >> 2);
        int gr1 = gr0 + 8;
#pragma unroll
        for (int f = 0; f < 4; f++) {
            int col0 = nbase + warpN * 32 + f * 8 + (lane & 3) * 2;
            float b0 = __ldg(&bias[col0]);
            float b1 = __ldg(&bias[col0 + 1]);
            float o[4];
#pragma unroll
            for (int r = 0; r < 4; r++) {
                float z = c[fm][f][r];
                float z0 = __shfl_sync(0xffffffffu, z, lane & 3);
                float h = tanhf(z0 + ((r & 1) ? b1 : b0));
                float g = 1.f - h * h;
                float d = __shfl_sync(0xffffffffu, z, dl);
                o[r] = (v == 0) ? h
                     : (v <= 4) ? g * z
                                : g * fmaf(-2.f * h * d, d, z);
            }
            __nv_bfloat16 h0, l0, h1, l1;
            bf16_split(o[0], h0, l0);
            bf16_split(o[1], h1, l1);
            *(uint32_t*)(Ohi + (size_t)gr0 * HDIM + col0) =
                (uint32_t)__bfloat16_as_ushort(h0) |
                ((uint32_t)__bfloat16_as_ushort(h1) << 16);
            *(uint32_t*)(Olo + (size_t)gr0 * HDIM + col0) =
                (uint32_t)__bfloat16_as_ushort(l0) |
                ((uint32_t)__bfloat16_as_ushort(l1) << 16);
            bf16_split(o[2], h0, l0);
            bf16_split(o[3], h1, l1);
            *(uint32_t*)(Ohi + (size_t)gr1 * HDIM + col0) =
                (uint32_t)__bfloat16_as_ushort(h0) |
                ((uint32_t)__bfloat16_as_ushort(h1) << 16);
            *(uint32_t*)(Olo + (size_t)gr1 * HDIM + col0) =
                (uint32_t)__bfloat16_as_ushort(l0) |
                ((uint32_t)__bfloat16_as_ushort(l1) << 16);
        }
    }
}

// ---------------------------------------------------------------------------
// Output head + physics (one warp per sample); cmode=2 layout verified R4.
// ---------------------------------------------------------------------------
__global__ void final_kernel(const __nv_bfloat16* __restrict__ Shi,
                             const __nv_bfloat16* __restrict__ Slo,
                             const float* __restrict__ Wo,
                             const float* __restrict__ bo,
                             const float* __restrict__ sc0,
                             const float* __restrict__ sc1,
                             const float* __restrict__ sc2,
                             float* __restrict__ out,
                             int Bn, int cmode)
{
    int gw   = (blockIdx.x * blockDim.x + threadIdx.x) >> 5;
    int lane = threadIdx.x & 31;
    if (gw >= Bn) return;

    size_t sb = (size_t)gw * (NVEC * HDIM);
    float acc[8][5];
#pragma unroll
    for (int v = 0; v < 8; v++)
#pragma unroll
        for (int o = 0; o < 5; o++) acc[v][o] = 0.f;

    for (int q = 0; q < 16; q++) {
        int j = lane + (q << 5);
        float wo0 = Wo[j * 5 + 0], wo1 = Wo[j * 5 + 1], wo2 = Wo[j * 5 + 2];
        float wo3 = Wo[j * 5 + 3], wo4 = Wo[j * 5 + 4];
#pragma unroll
        for (int v = 0; v < 8; v++) {
            size_t off = sb + (size_t)v * HDIM + j;
            float sv = __bfloat162float(Shi[off]) + __bfloat162float(Slo[off]);
            acc[v][0] = fmaf(sv, wo0, acc[v][0]);
            acc[v][1] = fmaf(sv, wo1, acc[v][1]);
            acc[v][2] = fmaf(sv, wo2, acc[v][2]);
            acc[v][3] = fmaf(sv, wo3, acc[v][3]);
            acc[v][4] = fmaf(sv, wo4, acc[v][4]);
        }
    }
#pragma unroll
    for (int v = 0; v < 8; v++)
#pragma unroll
        for (int o = 0; o < 5; o++) {
            float a = acc[v][o];
            a += __shfl_xor_sync(0xffffffffu, a, 16);
            a += __shfl_xor_sync(0xffffffffu, a, 8);
            a += __shfl_xor_sync(0xffffffffu, a, 4);
            a += __shfl_xor_sync(0xffffffffu, a, 2);
            a += __shfl_xor_sync(0xffffffffu, a, 1);
            acc[v][o] = a;
        }

    if (lane != 0) return;

    float sa = *sc0, sb2 = *sc1, sc = *sc2;
    float hbar = fmaxf(sa, fmaxf(sb2, sc));
    float visc = fminf(sa, fminf(sb2, sc));
    float coup = (sa + sb2 + sc) - hbar - visc;

    float ov[5], jac[5][4], lap[5];
#pragma unroll
    for (int o = 0; o < 5; o++) {
        ov[o] = acc[0][o] + bo[o];
#pragma unroll
        for (int i = 0; i < 4; i++) jac[o][i] = acc[1 + i][o];
        lap[o] = acc[5][o] + acc[6][o] + acc[7][o];
    }

    float pr = ov[0], pim = ov[1];
    float u0 = ov[2], u1 = ov[3], u2 = ov[4];
    float half_h2 = 0.5f * hbar * hbar;

    float qr = -hbar * jac[1][3] + half_h2 * lap[0];
    float qi =  hbar * jac[0][3] + half_h2 * lap[1];
    float rho = pr * pr + pim * pim;

    float pc[3], ns[3];
#pragma unroll
    for (int i = 0; i < 3; i++) {
        float conv = u0 * jac[2 + i][0] + u1 * jac[2 + i][1] + u2 * jac[2 + i][2];
        pc[i] = pr * jac[0][i] + pim * jac[1][i];
        float ui = ov[2 + i];
        float ct = coup * (pc[i] - ui * rho);
        ns[i] = jac[2 + i][3] + conv - visc * lap[2 + i] - ct;
    }
    float divg  = jac[2][0] + jac[3][1] + jac[4][2];
    float phase = atan2f(pim, pr);

    if (cmode == 2) {
        out[gw] = pr;
        out[Bn + gw * 3 + 0] = u0;
        out[Bn + gw * 3 + 1] = u1;
        out[Bn + gw * 3 + 2] = u2;
        out[4 * Bn + gw] = qr;
        out[5 * Bn + gw * 3 + 0] = ns[0];
        out[5 * Bn + gw * 3 + 1] = ns[1];
        out[5 * Bn + gw * 3 + 2] = ns[2];
        out[8 * Bn + gw]  = divg;
        out[9 * Bn + gw]  = rho;
        out[10 * Bn + gw] = phase;
        out[11 * Bn + gw * 3 + 0] = pc[0];
        out[11 * Bn + gw * 3 + 1] = pc[1];
        out[11 * Bn + gw * 3 + 2] = pc[2];
    } else if (cmode == 1) {
        float2* o2 = (float2*)out;
        o2[gw] = make_float2(pr, pim);
        o2[Bn + gw * 3 + 0] = make_float2(u0, 0.f);
        o2[Bn + gw * 3 + 1] = make_float2(u1, 0.f);
        o2[Bn + gw * 3 + 2] = make_float2(u2, 0.f);
        o2[4 * Bn + gw] = make_float2(qr, qi);
        o2[5 * Bn + gw * 3 + 0] = make_float2(ns[0], 0.f);
        o2[5 * Bn + gw * 3 + 1] = make_float2(ns[1], 0.f);
        o2[5 * Bn + gw * 3 + 2] = make_float2(ns[2], 0.f);
        o2[8 * Bn + gw]  = make_float2(divg, 0.f);
        o2[9 * Bn + gw]  = make_float2(rho, 0.f);
        o2[10 * Bn + gw] = make_float2(phase, 0.f);
        o2[11 * Bn + gw * 3 + 0] = make_float2(pc[0], 0.f);
        o2[11 * Bn + gw * 3 + 1] = make_float2(pc[1], 0.f);
        o2[11 * Bn + gw * 3 + 2] = make_float2(pc[2], 0.f);
    } else {
        out[2 * gw + 0] = pr;
        out[2 * gw + 1] = pim;
        out[2 * Bn + gw * 3 + 0] = u0;
        out[2 * Bn + gw * 3 + 1] = u1;
        out[2 * Bn + gw * 3 + 2] = u2;
        out[5 * Bn + 2 * gw + 0] = qr;
        out[5 * Bn + 2 * gw + 1] = qi;
        out[7 * Bn + gw * 3 + 0] = ns[0];
        out[7 * Bn + gw * 3 + 1] = ns[1];
        out[7 * Bn + gw * 3 + 2] = ns[2];
        out[10 * Bn + gw] = divg;
        out[11 * Bn + gw] = rho;
        out[12 * Bn + gw] = phase;
        out[13 * Bn + gw * 3 + 0] = pc[0];
        out[13 * Bn + gw * 3 + 1] = pc[1];
        out[13 * Bn + gw * 3 + 2] = pc[2];
    }
}

// ---------------------------------------------------------------------------
extern "C" void kernel_launch(void* const* d_in, const int* in_sizes, int n_in,
                              void* d_out, int out_size)
{
    const float *x = 0, *W0 = 0, *b0 = 0, *Wh = 0, *bh = 0, *Wo = 0, *bo = 0;
    const float* scal[3] = {0, 0, 0};
    int ns = 0;
    int Bn = 0;

    for (int i = 0; i < n_in; i++) {
        const float* p = (const float*)d_in[i];
        switch (in_sizes[i]) {
            case 8192 * 4:        x  = p; Bn = in_sizes[i] / 4; break;
            case 4 * 512:         W0 = p; break;
            case 512:             b0 = p; break;
            case 6 * 512 * 512:   Wh = p; break;
            case 6 * 512:         bh = p; break;
            case 512 * 5:         Wo = p; break;
            case 5:               bo = p; break;
            case 1:  if (ns < 3) scal[ns++] = p; break;
            default: break;
        }
    }
    if (!x || !W0 || !b0 || !Wh || !bh || !Wo || !bo || ns < 3) {
        x  = (const float*)d_in[0];  W0 = (const float*)d_in[1];
        b0 = (const float*)d_in[2];  Wh = (const float*)d_in[3];
        bh = (const float*)d_in[4];  Wo = (const float*)d_in[5];
        bo = (const float*)d_in[6];
        scal[0] = (const float*)d_in[7];
        scal[1] = (const float*)d_in[8];
        scal[2] = (const float*)d_in[9];
        Bn = in_sizes[0] / 4;
    }
    if (Bn <= 0 || Bn > MAXB) Bn = MAXB;

    __nv_bfloat16 *Ahi, *Alo, *Wth, *Wtl;
    cudaGetSymbolAddress((void**)&Ahi, g_Ahi);
    cudaGetSymbolAddress((void**)&Alo, g_Alo);
    cudaGetSymbolAddress((void**)&Wth, g_Wth);
    cudaGetSymbolAddress((void**)&Wtl, g_Wtl);

    cudaFuncSetAttribute(layer_mma_kernel,
                         cudaFuncAttributeMaxDynamicSharedMemorySize,
                         SMEM_TOTAL);

    prep_w_kernel<<<(6 * HDIM * HDIM + 255) / 256, 256>>>(Wh, Wth, Wtl);
    init_kernel<<<(Bn * HDIM + 255) / 256, 256>>>(x, W0, b0, Ahi, Alo, Bn);

    dim3 grid(HDIM / TN, (Bn * NVEC) / TM);
    int cur = 0;
    for (int l = 0; l < 6; l++) {
        int nxt = cur ^ 1;
        layer_mma_kernel<<<grid, 512, SMEM_TOTAL>>>(
            Ahi + (size_t)cur * PLANE, Alo + (size_t)cur * PLANE,
            Wth + (size_t)l * HDIM * HDIM, Wtl + (size_t)l * HDIM * HDIM,
            bh + (size_t)l * HDIM,
            Ahi + (size_t)nxt * PLANE, Alo + (size_t)nxt * PLANE);
        cur = nxt;
    }

    int cmode;
    if      (out_size == 14 * Bn) cmode = 2;
    else if (out_size == 16 * Bn) cmode = 0;
    else if (out_size == 28 * Bn) cmode = 1;
    else                          cmode = 2;

    final_kernel<<<(Bn + 7) / 8, 256>>>(Ahi + (size_t)cur * PLANE,
                                        Alo + (size_t)cur * PLANE,
                                        Wo, bo, scal[0], scal[1], scal[2],
                                        (float*)d_out, Bn, cmode);
}

// round 15
// speedup vs baseline: 1.2125x; 1.2125x over previous
#include <cuda_runtime.h>
#include <cuda_bf16.h>
#include <math.h>
#include <stdint.h>

// ---------------------------------------------------------------------------
// CosmopsychiaPINN via forward-mode Taylor propagation.
// Hidden layers: warp-level bf16 mma.sync (m16n8k16) split-GEMM, 3 passes:
//   C = Ahi*Whi + Ahi*Wlo + Alo*Whi   (fp32 accumulate)
// R15 = R12 config (256 thr, warp tile 32x64, cp.async 2-stage) +
// B-fragment register double-buffering: prefetch B(p+1) before MMAs of p,
// so ldmatrix latency is covered by tensor work (de-serializes the per-warp
// load/MMA phases). MMA order per accumulator identical to R12.
// Layer GEMM: M=8*B=65536, N=512, K=512.  (tcgen05 unusable: sm_100 target.)
// ---------------------------------------------------------------------------

#define HDIM 512
#define NVEC 8
#define MAXB 8192
#define TM   64
#define TN   256
#define KCH  32
#define PLANE ((size_t)NVEC * MAXB * HDIM)

#define ROWP 40
#define A_PLANE_BYTES (TM * ROWP * 2)     // 5120
#define B_PLANE_BYTES (TN * ROWP * 2)     // 20480
#define STAGE_BYTES (2 * A_PLANE_BYTES + 2 * B_PLANE_BYTES)  // 51200
#define SMEM_TOTAL (2 * STAGE_BYTES)                          // 102400

__device__ __nv_bfloat16 g_Ahi[2][PLANE];
__device__ __nv_bfloat16 g_Alo[2][PLANE];
__device__ __nv_bfloat16 g_Wth[6 * HDIM * HDIM];
__device__ __nv_bfloat16 g_Wtl[6 * HDIM * HDIM];

__device__ __forceinline__ uint32_t smem_u32(const void* p) {
    uint32_t a;
    asm("{ .reg .u64 t; cvta.to.shared.u64 t, %1; cvt.u32.u64 %0, t; }"
        : "=r"(a) : "l"(p));
    return a;
}
__device__ __forceinline__ void cp16(uint32_t dst, const void* src) {
    asm volatile("cp.async.cg.shared.global [%0], [%1], 16;"
                 :: "r"(dst), "l"(src) : "memory");
}
__device__ __forceinline__ void ldmx4(uint32_t* r, uint32_t addr) {
    asm volatile("ldmatrix.sync.aligned.m8n8.x4.shared.b16 {%0,%1,%2,%3}, [%4];"
                 : "=r"(r[0]), "=r"(r[1]), "=r"(r[2]), "=r"(r[3]) : "r"(addr));
}
__device__ __forceinline__ void mma16816(float* c, const uint32_t* a,
                                         const uint32_t* b) {
    asm volatile(
        "mma.sync.aligned.m16n8k16.row.col.f32.bf16.bf16.f32 "
        "{%0,%1,%2,%3}, {%4,%5,%6,%7}, {%8,%9}, {%0,%1,%2,%3};"
        : "+f"(c[0]), "+f"(c[1]), "+f"(c[2]), "+f"(c[3])
        : "r"(a[0]), "r"(a[1]), "r"(a[2]), "r"(a[3]), "r"(b[0]), "r"(b[1]));
}
__device__ __forceinline__ void bf16_split(float f, __nv_bfloat16& hi,
                                           __nv_bfloat16& lo) {
    hi = __float2bfloat16(f);
    lo = __float2bfloat16(f - __bfloat162float(hi));
}

// ---------------------------------------------------------------------------
__global__ void prep_w_kernel(const float* __restrict__ Wh,
                              __nv_bfloat16* __restrict__ Wth,
                              __nv_bfloat16* __restrict__ Wtl)
{
    int idx = blockIdx.x * blockDim.x + threadIdx.x;
    if (idx >= 6 * HDIM * HDIM) return;
    int l = idx >> 18;
    int rem = idx & (HDIM * HDIM - 1);
    int n = rem >> 9;
    int k = rem & (HDIM - 1);
    float w = Wh[(size_t)l * HDIM * HDIM + (size_t)k * HDIM + n];
    __nv_bfloat16 hi, lo;
    bf16_split(w, hi, lo);
    Wth[idx] = hi;
    Wtl[idx] = lo;
}

// ---------------------------------------------------------------------------
__global__ void init_kernel(const float* __restrict__ x,
                            const float* __restrict__ W0,
                            const float* __restrict__ b0,
                            __nv_bfloat16* __restrict__ Shi,
                            __nv_bfloat16* __restrict__ Slo, int Bn)
{
    int idx = blockIdx.x * blockDim.x + threadIdx.x;
    if (idx >= Bn * HDIM) return;
    int s = idx >> 9;
    int j = idx & (HDIM - 1);

    float x0 = x[s * 4 + 0], x1 = x[s * 4 + 1];
    float x2 = x[s * 4 + 2], x3 = x[s * 4 + 3];
    float w0 = W0[0 * HDIM + j];
    float w1 = W0[1 * HDIM + j];
    float w2 = W0[2 * HDIM + j];
    float w3 = W0[3 * HDIM + j];

    float z = fmaf(x0, w0, fmaf(x1, w1, fmaf(x2, w2, fmaf(x3, w3, b0[j]))));
    float h = tanhf(z);
    float g = 1.f - h * h;

    float vals[8];
    vals[0] = h;
    vals[1] = g * w0;
    vals[2] = g * w1;
    vals[3] = g * w2;
    vals[4] = g * w3;
    vals[5] = -2.f * h * g * w0 * w0;
    vals[6] = -2.f * h * g * w1 * w1;
    vals[7] = -2.f * h * g * w2 * w2;

#pragma unroll
    for (int v = 0; v < 8; v++) {
        size_t off = (size_t)(s * 8 + v) * HDIM + j;
        __nv_bfloat16 hi, lo;
        bf16_split(vals[v], hi, lo);
        Shi[off] = hi;
        Slo[off] = lo;
    }
}

// ---------------------------------------------------------------------------
// Hidden layer: bf16 mma.sync 3-pass GEMM, cp.async double-buffered k-loop,
// register double-buffered B fragments.
// Grid (HDIM/TN=2, Mtot/TM=1024), 256 threads = 8 warps (2m x 4n),
// warp tile 32x64. Stage: Ahi|Alo (64x40 bf16) + Bhi|Blo (256x40 bf16).
// ---------------------------------------------------------------------------
__global__ void __launch_bounds__(256, 2)
layer_mma_kernel(const __nv_bfloat16* __restrict__ Ahi,
                 const __nv_bfloat16* __restrict__ Alo,
                 const __nv_bfloat16* __restrict__ Bhi,
                 const __nv_bfloat16* __restrict__ Blo,
                 const float* __restrict__ bias,
                 __nv_bfloat16* __restrict__ Ohi,
                 __nv_bfloat16* __restrict__ Olo)
{
    extern __shared__ char sm[];

    int t = threadIdx.x;
    int lane = t & 31;
    int wid = t >> 5;
    int warpM = wid >> 2;       // 0..1
    int warpN = wid & 3;        // 0..3
    int mbase = blockIdx.y * TM;
    int nbase = blockIdx.x * TN;

    int aRow = t >> 2, aKq = t & 3;
    uint32_t aSo = aRow * (ROWP * 2) + aKq * 16;
    size_t aGo = (size_t)(mbase + aRow) * HDIM + aKq * 8;

    uint32_t bSo[4];
    size_t bGo[4];
#pragma unroll
    for (int j = 0; j < 4; j++) {
        int i = t + 256 * j;
        int row = i >> 2, kq = i & 3;
        bSo[j] = row * (ROWP * 2) + kq * 16;
        bGo[j] = (size_t)(nbase + row) * HDIM + kq * 8;
    }

    uint32_t stageAddr[2];
    stageAddr[0] = smem_u32(sm);
    stageAddr[1] = stageAddr[0] + STAGE_BYTES;

    uint32_t aoff[2];
#pragma unroll
    for (int fm = 0; fm < 2; fm++)
        aoff[fm] = ((warpM * 32 + fm * 16 + (lane & 15)) * ROWP +
                    ((lane >> 4) & 1) * 8) * 2;
    uint32_t boff[4];
#pragma unroll
    for (int p = 0; p < 4; p++)
        boff[p] = ((warpN * 64 + p * 16 + (lane & 7) + ((lane >> 4) & 1) * 8)
                   * ROWP + ((lane >> 3) & 1) * 8) * 2;

    float c[2][8][4];
#pragma unroll
    for (int fm = 0; fm < 2; fm++)
#pragma unroll
        for (int f = 0; f < 8; f++)
#pragma unroll
            for (int r = 0; r < 4; r++) c[fm][f][r] = 0.f;

    // ---- prefetch chunk 0 into stage 0 ----
    {
        uint32_t sb = stageAddr[0];
        cp16(sb + aSo, Ahi + aGo);
        cp16(sb + A_PLANE_BYTES + aSo, Alo + aGo);
#pragma unroll
        for (int j = 0; j < 4; j++) {
            cp16(sb + 2 * A_PLANE_BYTES + bSo[j], Bhi + bGo[j]);
            cp16(sb + 2 * A_PLANE_BYTES + B_PLANE_BYTES + bSo[j], Blo + bGo[j]);
        }
        asm volatile("cp.async.commit_group;" ::: "memory");
    }

    const int NKCH = HDIM / KCH;   // 16
    for (int kc = 0; kc < NKCH; kc++) {
        int cur = kc & 1;
        asm volatile("cp.async.wait_group 0;" ::: "memory");
        __syncthreads();

        if (kc + 1 < NKCH) {
            uint32_t sb = stageAddr[cur ^ 1];
            size_t kofe = (size_t)(kc + 1) * KCH;
            cp16(sb + aSo, Ahi + aGo + kofe);
            cp16(sb + A_PLANE_BYTES + aSo, Alo + aGo + kofe);
#pragma unroll
            for (int j = 0; j < 4; j++) {
                cp16(sb + 2 * A_PLANE_BYTES + bSo[j], Bhi + bGo[j] + kofe);
                cp16(sb + 2 * A_PLANE_BYTES + B_PLANE_BYTES + bSo[j],
                     Blo + bGo[j] + kofe);
            }
            asm volatile("cp.async.commit_group;" ::: "memory");
        }

        uint32_t aBaseH = stageAddr[cur];
        uint32_t aBaseL = aBaseH + A_PLANE_BYTES;
        uint32_t bBaseH = aBaseH + 2 * A_PLANE_BYTES;
        uint32_t bBaseL = bBaseH + B_PLANE_BYTES;

#pragma unroll
        for (int kh = 0; kh < 2; kh++) {
            uint32_t kb2 = kh * 32;
            uint32_t ah[2][4], al[2][4];
#pragma unroll
            for (int fm = 0; fm < 2; fm++) {
                ldmx4(ah[fm], aBaseH + aoff[fm] + kb2);
                ldmx4(al[fm], aBaseL + aoff[fm] + kb2);
            }
            // Register double-buffer for B fragments.
            uint32_t bh[2][4], bl[2][4];
            ldmx4(bh[0], bBaseH + boff[0] + kb2);
            ldmx4(bl[0], bBaseL + boff[0] + kb2);
#pragma unroll
            for (int p = 0; p < 4; p++) {
                int cb = p & 1, nb = cb ^ 1;
                if (p < 3) {
                    // Prefetch next B pair BEFORE consuming current -> the
                    // 12 MMAs below cover the ldmatrix latency.
                    ldmx4(bh[nb], bBaseH + boff[p + 1] + kb2);
                    ldmx4(bl[nb], bBaseL + boff[p + 1] + kb2);
                }
#pragma unroll
                for (int fm = 0; fm < 2; fm++)
#pragma unroll
                    for (int q = 0; q < 2; q++) {
                        int f = 2 * p + q;
                        mma16816(c[fm][f], ah[fm], bh[cb] + 2 * q);
                        mma16816(c[fm][f], ah[fm], bl[cb] + 2 * q);
                        mma16816(c[fm][f], al[fm], bh[cb] + 2 * q);
                    }
            }
        }
    }

    // ---- epilogue: tanh-chain via warp shuffles, bf16 hi/lo stores ----
    int v = lane >> 2;
    int dl = (((v >= 5) ? (v - 4) : 0) << 2) | (lane & 3);
#pragma unroll
    for (int fm = 0; fm < 2; fm++) {
        int gr0 = mbase + warpM * 32 + fm * 16 + (lane >> 2);
        int gr1 = gr0 + 8;
#pragma unroll
        for (int f = 0; f < 8; f++) {
            int col0 = nbase + warpN * 64 + f * 8 + (lane & 3) * 2;
            float b0 = __ldg(&bias[col0]);
            float b1 = __ldg(&bias[col0 + 1]);
            float o[4];
#pragma unroll
            for (int r = 0; r < 4; r++) {
                float z = c[fm][f][r];
                float z0 = __shfl_sync(0xffffffffu, z, lane & 3);
                float h = tanhf(z0 + ((r & 1) ? b1 : b0));
                float g = 1.f - h * h;
                float d = __shfl_sync(0xffffffffu, z, dl);
                o[r] = (v == 0) ? h
                     : (v <= 4) ? g * z
                                : g * fmaf(-2.f * h * d, d, z);
            }
            __nv_bfloat16 h0, l0, h1, l1;
            bf16_split(o[0], h0, l0);
            bf16_split(o[1], h1, l1);
            *(uint32_t*)(Ohi + (size_t)gr0 * HDIM + col0) =
                (uint32_t)__bfloat16_as_ushort(h0) |
                ((uint32_t)__bfloat16_as_ushort(h1) << 16);
            *(uint32_t*)(Olo + (size_t)gr0 * HDIM + col0) =
                (uint32_t)__bfloat16_as_ushort(l0) |
                ((uint32_t)__bfloat16_as_ushort(l1) << 16);
            bf16_split(o[2], h0, l0);
            bf16_split(o[3], h1, l1);
            *(uint32_t*)(Ohi + (size_t)gr1 * HDIM + col0) =
                (uint32_t)__bfloat16_as_ushort(h0) |
                ((uint32_t)__bfloat16_as_ushort(h1) << 16);
            *(uint32_t*)(Olo + (size_t)gr1 * HDIM + col0) =
                (uint32_t)__bfloat16_as_ushort(l0) |
                ((uint32_t)__bfloat16_as_ushort(l1) << 16);
        }
    }
}

// ---------------------------------------------------------------------------
// Output head + physics (one warp per sample); cmode=2 layout verified R4.
// ---------------------------------------------------------------------------
__global__ void final_kernel(const __nv_bfloat16* __restrict__ Shi,
                             const __nv_bfloat16* __restrict__ Slo,
                             const float* __restrict__ Wo,
                             const float* __restrict__ bo,
                             const float* __restrict__ sc0,
                             const float* __restrict__ sc1,
                             const float* __restrict__ sc2,
                             float* __restrict__ out,
                             int Bn, int cmode)
{
    int gw   = (blockIdx.x * blockDim.x + threadIdx.x) >> 5;
    int lane = threadIdx.x & 31;
    if (gw >= Bn) return;

    size_t sb = (size_t)gw * (NVEC * HDIM);
    float acc[8][5];
#pragma unroll
    for (int v = 0; v < 8; v++)
#pragma unroll
        for (int o = 0; o < 5; o++) acc[v][o] = 0.f;

    for (int q = 0; q < 16; q++) {
        int j = lane + (q << 5);
        float wo0 = Wo[j * 5 + 0], wo1 = Wo[j * 5 + 1], wo2 = Wo[j * 5 + 2];
        float wo3 = Wo[j * 5 + 3], wo4 = Wo[j * 5 + 4];
#pragma unroll
        for (int v = 0; v < 8; v++) {
            size_t off = sb + (size_t)v * HDIM + j;
            float sv = __bfloat162float(Shi[off]) + __bfloat162float(Slo[off]);
            acc[v][0] = fmaf(sv, wo0, acc[v][0]);
            acc[v][1] = fmaf(sv, wo1, acc[v][1]);
            acc[v][2] = fmaf(sv, wo2, acc[v][2]);
            acc[v][3] = fmaf(sv, wo3, acc[v][3]);
            acc[v][4] = fmaf(sv, wo4, acc[v][4]);
        }
    }
#pragma unroll
    for (int v = 0; v < 8; v++)
#pragma unroll
        for (int o = 0; o < 5; o++) {
            float a = acc[v][o];
            a += __shfl_xor_sync(0xffffffffu, a, 16);
            a += __shfl_xor_sync(0xffffffffu, a, 8);
            a += __shfl_xor_sync(0xffffffffu, a, 4);
            a += __shfl_xor_sync(0xffffffffu, a, 2);
            a += __shfl_xor_sync(0xffffffffu, a, 1);
            acc[v][o] = a;
        }

    if (lane != 0) return;

    float sa = *sc0, sb2 = *sc1, sc = *sc2;
    float hbar = fmaxf(sa, fmaxf(sb2, sc));
    float visc = fminf(sa, fminf(sb2, sc));
    float coup = (sa + sb2 + sc) - hbar - visc;

    float ov[5], jac[5][4], lap[5];
#pragma unroll
    for (int o = 0; o < 5; o++) {
        ov[o] = acc[0][o] + bo[o];
#pragma unroll
        for (int i = 0; i < 4; i++) jac[o][i] = acc[1 + i][o];
        lap[o] = acc[5][o] + acc[6][o] + acc[7][o];
    }

    float pr = ov[0], pim = ov[1];
    float u0 = ov[2], u1 = ov[3], u2 = ov[4];
    float half_h2 = 0.5f * hbar * hbar;

    float qr = -hbar * jac[1][3] + half_h2 * lap[0];
    float qi =  hbar * jac[0][3] + half_h2 * lap[1];
    float rho = pr * pr + pim * pim;

    float pc[3], ns[3];
#pragma unroll
    for (int i = 0; i < 3; i++) {
        float conv = u0 * jac[2 + i][0] + u1 * jac[2 + i][1] + u2 * jac[2 + i][2];
        pc[i] = pr * jac[0][i] + pim * jac[1][i];
        float ui = ov[2 + i];
        float ct = coup * (pc[i] - ui * rho);
        ns[i] = jac[2 + i][3] + conv - visc * lap[2 + i] - ct;
    }
    float divg  = jac[2][0] + jac[3][1] + jac[4][2];
    float phase = atan2f(pim, pr);

    if (cmode == 2) {
        out[gw] = pr;
        out[Bn + gw * 3 + 0] = u0;
        out[Bn + gw * 3 + 1] = u1;
        out[Bn + gw * 3 + 2] = u2;
        out[4 * Bn + gw] = qr;
        out[5 * Bn + gw * 3 + 0] = ns[0];
        out[5 * Bn + gw * 3 + 1] = ns[1];
        out[5 * Bn + gw * 3 + 2] = ns[2];
        out[8 * Bn + gw]  = divg;
        out[9 * Bn + gw]  = rho;
        out[10 * Bn + gw] = phase;
        out[11 * Bn + gw * 3 + 0] = pc[0];
        out[11 * Bn + gw * 3 + 1] = pc[1];
        out[11 * Bn + gw * 3 + 2] = pc[2];
    } else if (cmode == 1) {
        float2* o2 = (float2*)out;
        o2[gw] = make_float2(pr, pim);
        o2[Bn + gw * 3 + 0] = make_float2(u0, 0.f);
        o2[Bn + gw * 3 + 1] = make_float2(u1, 0.f);
        o2[Bn + gw * 3 + 2] = make_float2(u2, 0.f);
        o2[4 * Bn + gw] = make_float2(qr, qi);
        o2[5 * Bn + gw * 3 + 0] = make_float2(ns[0], 0.f);
        o2[5 * Bn + gw * 3 + 1] = make_float2(ns[1], 0.f);
        o2[5 * Bn + gw * 3 + 2] = make_float2(ns[2], 0.f);
        o2[8 * Bn + gw]  = make_float2(divg, 0.f);
        o2[9 * Bn + gw]  = make_float2(rho, 0.f);
        o2[10 * Bn + gw] = make_float2(phase, 0.f);
        o2[11 * Bn + gw * 3 + 0] = make_float2(pc[0], 0.f);
        o2[11 * Bn + gw * 3 + 1] = make_float2(pc[1], 0.f);
        o2[11 * Bn + gw * 3 + 2] = make_float2(pc[2], 0.f);
    } else {
        out[2 * gw + 0] = pr;
        out[2 * gw + 1] = pim;
        out[2 * Bn + gw * 3 + 0] = u0;
        out[2 * Bn + gw * 3 + 1] = u1;
        out[2 * Bn + gw * 3 + 2] = u2;
        out[5 * Bn + 2 * gw + 0] = qr;
        out[5 * Bn + 2 * gw + 1] = qi;
        out[7 * Bn + gw * 3 + 0] = ns[0];
        out[7 * Bn + gw * 3 + 1] = ns[1];
        out[7 * Bn + gw * 3 + 2] = ns[2];
        out[10 * Bn + gw] = divg;
        out[11 * Bn + gw] = rho;
        out[12 * Bn + gw] = phase;
        out[13 * Bn + gw * 3 + 0] = pc[0];
        out[13 * Bn + gw * 3 + 1] = pc[1];
        out[13 * Bn + gw * 3 + 2] = pc[2];
    }
}

// ---------------------------------------------------------------------------
extern "C" void kernel_launch(void* const* d_in, const int* in_sizes, int n_in,
                              void* d_out, int out_size)
{
    const float *x = 0, *W0 = 0, *b0 = 0, *Wh = 0, *bh = 0, *Wo = 0, *bo = 0;
    const float* scal[3] = {0, 0, 0};
    int ns = 0;
    int Bn = 0;

    for (int i = 0; i < n_in; i++) {
        const float* p = (const float*)d_in[i];
        switch (in_sizes[i]) {
            case 8192 * 4:        x  = p; Bn = in_sizes[i] / 4; break;
            case 4 * 512:         W0 = p; break;
            case 512:             b0 = p; break;
            case 6 * 512 * 512:   Wh = p; break;
            case 6 * 512:         bh = p; break;
            case 512 * 5:         Wo = p; break;
            case 5:               bo = p; break;
            case 1:  if (ns < 3) scal[ns++] = p; break;
            default: break;
        }
    }
    if (!x || !W0 || !b0 || !Wh || !bh || !Wo || !bo || ns < 3) {
        x  = (const float*)d_in[0];  W0 = (const float*)d_in[1];
        b0 = (const float*)d_in[2];  Wh = (const float*)d_in[3];
        bh = (const float*)d_in[4];  Wo = (const float*)d_in[5];
        bo = (const float*)d_in[6];
        scal[0] = (const float*)d_in[7];
        scal[1] = (const float*)d_in[8];
        scal[2] = (const float*)d_in[9];
        Bn = in_sizes[0] / 4;
    }
    if (Bn <= 0 || Bn > MAXB) Bn = MAXB;

    __nv_bfloat16 *Ahi, *Alo, *Wth, *Wtl;
    cudaGetSymbolAddress((void**)&Ahi, g_Ahi);
    cudaGetSymbolAddress((void**)&Alo, g_Alo);
    cudaGetSymbolAddress((void**)&Wth, g_Wth);
    cudaGetSymbolAddress((void**)&Wtl, g_Wtl);

    cudaFuncSetAttribute(layer_mma_kernel,
                         cudaFuncAttributeMaxDynamicSharedMemorySize,
                         SMEM_TOTAL);

    prep_w_kernel<<<(6 * HDIM * HDIM + 255) / 256, 256>>>(Wh, Wth, Wtl);
    init_kernel<<<(Bn * HDIM + 255) / 256, 256>>>(x, W0, b0, Ahi, Alo, Bn);

    dim3 grid(HDIM / TN, (Bn * NVEC) / TM);
    int cur = 0;
    for (int l = 0; l < 6; l++) {
        int nxt = cur ^ 1;
        layer_mma_kernel<<<grid, 256, SMEM_TOTAL>>>(
            Ahi + (size_t)cur * PLANE, Alo + (size_t)cur * PLANE,
            Wth + (size_t)l * HDIM * HDIM, Wtl + (size_t)l * HDIM * HDIM,
            bh + (size_t)l * HDIM,
            Ahi + (size_t)nxt * PLANE, Alo + (size_t)nxt * PLANE);
        cur = nxt;
    }

    int cmode;
    if      (out_size == 14 * Bn) cmode = 2;
    else if (out_size == 16 * Bn) cmode = 0;
    else if (out_size == 28 * Bn) cmode = 1;
    else                          cmode = 2;

    final_kernel<<<(Bn + 7) / 8, 256>>>(Ahi + (size_t)cur * PLANE,
                                        Alo + (size_t)cur * PLANE,
                                        Wo, bo, scal[0], scal[1], scal[2],
                                        (float*)d_out, Bn, cmode);
}

// round 17
// speedup vs baseline: 1.2128x; 1.0003x over previous
#include <cuda_runtime.h>
#include <cuda_bf16.h>
#include <math.h>
#include <stdint.h>

// ---------------------------------------------------------------------------
// CosmopsychiaPINN via forward-mode Taylor propagation.
// Hidden layers: warp-level bf16 mma.sync (m16n8k16) split-GEMM, 3 passes:
//   C = Ahi*Whi + Ahi*Wlo + Alo*Whi   (fp32 accumulate)
// R17 = R16 resubmit (broker infra failure; kernel never ran):
// intra-p pass-major MMA order — the 12 MMAs of each B-fragment pair are
// issued as 4x(hh), 4x(hl), 4x(lh) -> dependent MMAs on the same accumulator
// are 4 apart (was back-to-back chains of 3). Zero register delta;
// per-accumulator product order unchanged (bit-identical results).
// Layer GEMM: M=8*B=65536, N=512, K=512.  (tcgen05 unusable: sm_100 target.)
// ---------------------------------------------------------------------------

#define HDIM 512
#define NVEC 8
#define MAXB 8192
#define TM   64
#define TN   256
#define KCH  32
#define PLANE ((size_t)NVEC * MAXB * HDIM)

#define ROWP 40
#define A_PLANE_BYTES (TM * ROWP * 2)     // 5120
#define B_PLANE_BYTES (TN * ROWP * 2)     // 20480
#define STAGE_BYTES (2 * A_PLANE_BYTES + 2 * B_PLANE_BYTES)  // 51200
#define SMEM_TOTAL (2 * STAGE_BYTES)                          // 102400

__device__ __nv_bfloat16 g_Ahi[2][PLANE];
__device__ __nv_bfloat16 g_Alo[2][PLANE];
__device__ __nv_bfloat16 g_Wth[6 * HDIM * HDIM];
__device__ __nv_bfloat16 g_Wtl[6 * HDIM * HDIM];

__device__ __forceinline__ uint32_t smem_u32(const void* p) {
    uint32_t a;
    asm("{ .reg .u64 t; cvta.to.shared.u64 t, %1; cvt.u32.u64 %0, t; }"
        : "=r"(a) : "l"(p));
    return a;
}
__device__ __forceinline__ void cp16(uint32_t dst, const void* src) {
    asm volatile("cp.async.cg.shared.global [%0], [%1], 16;"
                 :: "r"(dst), "l"(src) : "memory");
}
__device__ __forceinline__ void ldmx4(uint32_t* r, uint32_t addr) {
    asm volatile("ldmatrix.sync.aligned.m8n8.x4.shared.b16 {%0,%1,%2,%3}, [%4];"
                 : "=r"(r[0]), "=r"(r[1]), "=r"(r[2]), "=r"(r[3]) : "r"(addr));
}
__device__ __forceinline__ void mma16816(float* c, const uint32_t* a,
                                         const uint32_t* b) {
    asm volatile(
        "mma.sync.aligned.m16n8k16.row.col.f32.bf16.bf16.f32 "
        "{%0,%1,%2,%3}, {%4,%5,%6,%7}, {%8,%9}, {%0,%1,%2,%3};"
        : "+f"(c[0]), "+f"(c[1]), "+f"(c[2]), "+f"(c[3])
        : "r"(a[0]), "r"(a[1]), "r"(a[2]), "r"(a[3]), "r"(b[0]), "r"(b[1]));
}
__device__ __forceinline__ void bf16_split(float f, __nv_bfloat16& hi,
                                           __nv_bfloat16& lo) {
    hi = __float2bfloat16(f);
    lo = __float2bfloat16(f - __bfloat162float(hi));
}

// ---------------------------------------------------------------------------
__global__ void prep_w_kernel(const float* __restrict__ Wh,
                              __nv_bfloat16* __restrict__ Wth,
                              __nv_bfloat16* __restrict__ Wtl)
{
    int idx = blockIdx.x * blockDim.x + threadIdx.x;
    if (idx >= 6 * HDIM * HDIM) return;
    int l = idx >> 18;
    int rem = idx & (HDIM * HDIM - 1);
    int n = rem >> 9;
    int k = rem & (HDIM - 1);
    float w = Wh[(size_t)l * HDIM * HDIM + (size_t)k * HDIM + n];
    __nv_bfloat16 hi, lo;
    bf16_split(w, hi, lo);
    Wth[idx] = hi;
    Wtl[idx] = lo;
}

// ---------------------------------------------------------------------------
__global__ void init_kernel(const float* __restrict__ x,
                            const float* __restrict__ W0,
                            const float* __restrict__ b0,
                            __nv_bfloat16* __restrict__ Shi,
                            __nv_bfloat16* __restrict__ Slo, int Bn)
{
    int idx = blockIdx.x * blockDim.x + threadIdx.x;
    if (idx >= Bn * HDIM) return;
    int s = idx >> 9;
    int j = idx & (HDIM - 1);

    float x0 = x[s * 4 + 0], x1 = x[s * 4 + 1];
    float x2 = x[s * 4 + 2], x3 = x[s * 4 + 3];
    float w0 = W0[0 * HDIM + j];
    float w1 = W0[1 * HDIM + j];
    float w2 = W0[2 * HDIM + j];
    float w3 = W0[3 * HDIM + j];

    float z = fmaf(x0, w0, fmaf(x1, w1, fmaf(x2, w2, fmaf(x3, w3, b0[j]))));
    float h = tanhf(z);
    float g = 1.f - h * h;

    float vals[8];
    vals[0] = h;
    vals[1] = g * w0;
    vals[2] = g * w1;
    vals[3] = g * w2;
    vals[4] = g * w3;
    vals[5] = -2.f * h * g * w0 * w0;
    vals[6] = -2.f * h * g * w1 * w1;
    vals[7] = -2.f * h * g * w2 * w2;

#pragma unroll
    for (int v = 0; v < 8; v++) {
        size_t off = (size_t)(s * 8 + v) * HDIM + j;
        __nv_bfloat16 hi, lo;
        bf16_split(vals[v], hi, lo);
        Shi[off] = hi;
        Slo[off] = lo;
    }
}

// ---------------------------------------------------------------------------
// Hidden layer: bf16 mma.sync 3-pass GEMM, cp.async double-buffered k-loop,
// register double-buffered B fragments, pass-major intra-p MMA order.
// Grid (HDIM/TN=2, Mtot/TM=1024), 256 threads = 8 warps (2m x 4n),
// warp tile 32x64. Stage: Ahi|Alo (64x40 bf16) + Bhi|Blo (256x40 bf16).
// ---------------------------------------------------------------------------
__global__ void __launch_bounds__(256, 2)
layer_mma_kernel(const __nv_bfloat16* __restrict__ Ahi,
                 const __nv_bfloat16* __restrict__ Alo,
                 const __nv_bfloat16* __restrict__ Bhi,
                 const __nv_bfloat16* __restrict__ Blo,
                 const float* __restrict__ bias,
                 __nv_bfloat16* __restrict__ Ohi,
                 __nv_bfloat16* __restrict__ Olo)
{
    extern __shared__ char sm[];

    int t = threadIdx.x;
    int lane = t & 31;
    int wid = t >> 5;
    int warpM = wid >> 2;       // 0..1
    int warpN = wid & 3;        // 0..3
    int mbase = blockIdx.y * TM;
    int nbase = blockIdx.x * TN;

    int aRow = t >> 2, aKq = t & 3;
    uint32_t aSo = aRow * (ROWP * 2) + aKq * 16;
    size_t aGo = (size_t)(mbase + aRow) * HDIM + aKq * 8;

    uint32_t bSo[4];
    size_t bGo[4];
#pragma unroll
    for (int j = 0; j < 4; j++) {
        int i = t + 256 * j;
        int row = i >> 2, kq = i & 3;
        bSo[j] = row * (ROWP * 2) + kq * 16;
        bGo[j] = (size_t)(nbase + row) * HDIM + kq * 8;
    }

    uint32_t stageAddr[2];
    stageAddr[0] = smem_u32(sm);
    stageAddr[1] = stageAddr[0] + STAGE_BYTES;

    uint32_t aoff[2];
#pragma unroll
    for (int fm = 0; fm < 2; fm++)
        aoff[fm] = ((warpM * 32 + fm * 16 + (lane & 15)) * ROWP +
                    ((lane >> 4) & 1) * 8) * 2;
    uint32_t boff[4];
#pragma unroll
    for (int p = 0; p < 4; p++)
        boff[p] = ((warpN * 64 + p * 16 + (lane & 7) + ((lane >> 4) & 1) * 8)
                   * ROWP + ((lane >> 3) & 1) * 8) * 2;

    float c[2][8][4];
#pragma unroll
    for (int fm = 0; fm < 2; fm++)
#pragma unroll
        for (int f = 0; f < 8; f++)
#pragma unroll
            for (int r = 0; r < 4; r++) c[fm][f][r] = 0.f;

    // ---- prefetch chunk 0 into stage 0 ----
    {
        uint32_t sb = stageAddr[0];
        cp16(sb + aSo, Ahi + aGo);
        cp16(sb + A_PLANE_BYTES + aSo, Alo + aGo);
#pragma unroll
        for (int j = 0; j < 4; j++) {
            cp16(sb + 2 * A_PLANE_BYTES + bSo[j], Bhi + bGo[j]);
            cp16(sb + 2 * A_PLANE_BYTES + B_PLANE_BYTES + bSo[j], Blo + bGo[j]);
        }
        asm volatile("cp.async.commit_group;" ::: "memory");
    }

    const int NKCH = HDIM / KCH;   // 16
    for (int kc = 0; kc < NKCH; kc++) {
        int cur = kc & 1;
        asm volatile("cp.async.wait_group 0;" ::: "memory");
        __syncthreads();

        if (kc + 1 < NKCH) {
            uint32_t sb = stageAddr[cur ^ 1];
            size_t kofe = (size_t)(kc + 1) * KCH;
            cp16(sb + aSo, Ahi + aGo + kofe);
            cp16(sb + A_PLANE_BYTES + aSo, Alo + aGo + kofe);
#pragma unroll
            for (int j = 0; j < 4; j++) {
                cp16(sb + 2 * A_PLANE_BYTES + bSo[j], Bhi + bGo[j] + kofe);
                cp16(sb + 2 * A_PLANE_BYTES + B_PLANE_BYTES + bSo[j],
                     Blo + bGo[j] + kofe);
            }
            asm volatile("cp.async.commit_group;" ::: "memory");
        }

        uint32_t aBaseH = stageAddr[cur];
        uint32_t aBaseL = aBaseH + A_PLANE_BYTES;
        uint32_t bBaseH = aBaseH + 2 * A_PLANE_BYTES;
        uint32_t bBaseL = bBaseH + B_PLANE_BYTES;

#pragma unroll
        for (int kh = 0; kh < 2; kh++) {
            uint32_t kb2 = kh * 32;
            uint32_t ah[2][4], al[2][4];
#pragma unroll
            for (int fm = 0; fm < 2; fm++) {
                ldmx4(ah[fm], aBaseH + aoff[fm] + kb2);
                ldmx4(al[fm], aBaseL + aoff[fm] + kb2);
            }
            // Register double-buffer for B fragments.
            uint32_t bh[2][4], bl[2][4];
            ldmx4(bh[0], bBaseH + boff[0] + kb2);
            ldmx4(bl[0], bBaseL + boff[0] + kb2);
#pragma unroll
            for (int p = 0; p < 4; p++) {
                int cb = p & 1, nb = cb ^ 1;
                if (p < 3) {
                    ldmx4(bh[nb], bBaseH + boff[p + 1] + kb2);
                    ldmx4(bl[nb], bBaseL + boff[p + 1] + kb2);
                }
                // Pass-major within p: 4 independent MMAs per pass ->
                // same-accumulator dependents are 4 apart (was 1).
#pragma unroll
                for (int fm = 0; fm < 2; fm++)
#pragma unroll
                    for (int q = 0; q < 2; q++)
                        mma16816(c[fm][2 * p + q], ah[fm], bh[cb] + 2 * q);
#pragma unroll
                for (int fm = 0; fm < 2; fm++)
#pragma unroll
                    for (int q = 0; q < 2; q++)
                        mma16816(c[fm][2 * p + q], ah[fm], bl[cb] + 2 * q);
#pragma unroll
                for (int fm = 0; fm < 2; fm++)
#pragma unroll
                    for (int q = 0; q < 2; q++)
                        mma16816(c[fm][2 * p + q], al[fm], bh[cb] + 2 * q);
            }
        }
    }

    // ---- epilogue: tanh-chain via warp shuffles, bf16 hi/lo stores ----
    int v = lane >> 2;
    int dl = (((v >= 5) ? (v - 4) : 0) << 2) | (lane & 3);
#pragma unroll
    for (int fm = 0; fm < 2; fm++) {
        int gr0 = mbase + warpM * 32 + fm * 16 + (lane >> 2);
        int gr1 = gr0 + 8;
#pragma unroll
        for (int f = 0; f < 8; f++) {
            int col0 = nbase + warpN * 64 + f * 8 + (lane & 3) * 2;
            float b0 = __ldg(&bias[col0]);
            float b1 = __ldg(&bias[col0 + 1]);
            float o[4];
#pragma unroll
            for (int r = 0; r < 4; r++) {
                float z = c[fm][f][r];
                float z0 = __shfl_sync(0xffffffffu, z, lane & 3);
                float h = tanhf(z0 + ((r & 1) ? b1 : b0));
                float g = 1.f - h * h;
                float d = __shfl_sync(0xffffffffu, z, dl);
                o[r] = (v == 0) ? h
                     : (v <= 4) ? g * z
                                : g * fmaf(-2.f * h * d, d, z);
            }
            __nv_bfloat16 h0, l0, h1, l1;
            bf16_split(o[0], h0, l0);
            bf16_split(o[1], h1, l1);
            *(uint32_t*)(Ohi + (size_t)gr0 * HDIM + col0) =
                (uint32_t)__bfloat16_as_ushort(h0) |
                ((uint32_t)__bfloat16_as_ushort(h1) << 16);
            *(uint32_t*)(Olo + (size_t)gr0 * HDIM + col0) =
                (uint32_t)__bfloat16_as_ushort(l0) |
                ((uint32_t)__bfloat16_as_ushort(l1) << 16);
            bf16_split(o[2], h0, l0);
            bf16_split(o[3], h1, l1);
            *(uint32_t*)(Ohi + (size_t)gr1 * HDIM + col0) =
                (uint32_t)__bfloat16_as_ushort(h0) |
                ((uint32_t)__bfloat16_as_ushort(h1) << 16);
            *(uint32_t*)(Olo + (size_t)gr1 * HDIM + col0) =
                (uint32_t)__bfloat16_as_ushort(l0) |
                ((uint32_t)__bfloat16_as_ushort(l1) << 16);
        }
    }
}

// ---------------------------------------------------------------------------
// Output head + physics (one warp per sample); cmode=2 layout verified R4.
// ---------------------------------------------------------------------------
__global__ void final_kernel(const __nv_bfloat16* __restrict__ Shi,
                             const __nv_bfloat16* __restrict__ Slo,
                             const float* __restrict__ Wo,
                             const float* __restrict__ bo,
                             const float* __restrict__ sc0,
                             const float* __restrict__ sc1,
                             const float* __restrict__ sc2,
                             float* __restrict__ out,
                             int Bn, int cmode)
{
    int gw   = (blockIdx.x * blockDim.x + threadIdx.x) >> 5;
    int lane = threadIdx.x & 31;
    if (gw >= Bn) return;

    size_t sb = (size_t)gw * (NVEC * HDIM);
    float acc[8][5];
#pragma unroll
    for (int v = 0; v < 8; v++)
#pragma unroll
        for (int o = 0; o < 5; o++) acc[v][o] = 0.f;

    for (int q = 0; q < 16; q++) {
        int j = lane + (q << 5);
        float wo0 = Wo[j * 5 + 0], wo1 = Wo[j * 5 + 1], wo2 = Wo[j * 5 + 2];
        float wo3 = Wo[j * 5 + 3], wo4 = Wo[j * 5 + 4];
#pragma unroll
        for (int v = 0; v < 8; v++) {
            size_t off = sb + (size_t)v * HDIM + j;
            float sv = __bfloat162float(Shi[off]) + __bfloat162float(Slo[off]);
            acc[v][0] = fmaf(sv, wo0, acc[v][0]);
            acc[v][1] = fmaf(sv, wo1, acc[v][1]);
            acc[v][2] = fmaf(sv, wo2, acc[v][2]);
            acc[v][3] = fmaf(sv, wo3, acc[v][3]);
            acc[v][4] = fmaf(sv, wo4, acc[v][4]);
        }
    }
#pragma unroll
    for (int v = 0; v < 8; v++)
#pragma unroll
        for (int o = 0; o < 5; o++) {
            float a = acc[v][o];
            a += __shfl_xor_sync(0xffffffffu, a, 16);
            a += __shfl_xor_sync(0xffffffffu, a, 8);
            a += __shfl_xor_sync(0xffffffffu, a, 4);
            a += __shfl_xor_sync(0xffffffffu, a, 2);
            a += __shfl_xor_sync(0xffffffffu, a, 1);
            acc[v][o] = a;
        }

    if (lane != 0) return;

    float sa = *sc0, sb2 = *sc1, sc = *sc2;
    float hbar = fmaxf(sa, fmaxf(sb2, sc));
    float visc = fminf(sa, fminf(sb2, sc));
    float coup = (sa + sb2 + sc) - hbar - visc;

    float ov[5], jac[5][4], lap[5];
#pragma unroll
    for (int o = 0; o < 5; o++) {
        ov[o] = acc[0][o] + bo[o];
#pragma unroll
        for (int i = 0; i < 4; i++) jac[o][i] = acc[1 + i][o];
        lap[o] = acc[5][o] + acc[6][o] + acc[7][o];
    }

    float pr = ov[0], pim = ov[1];
    float u0 = ov[2], u1 = ov[3], u2 = ov[4];
    float half_h2 = 0.5f * hbar * hbar;

    float qr = -hbar * jac[1][3] + half_h2 * lap[0];
    float qi =  hbar * jac[0][3] + half_h2 * lap[1];
    float rho = pr * pr + pim * pim;

    float pc[3], ns[3];
#pragma unroll
    for (int i = 0; i < 3; i++) {
        float conv = u0 * jac[2 + i][0] + u1 * jac[2 + i][1] + u2 * jac[2 + i][2];
        pc[i] = pr * jac[0][i] + pim * jac[1][i];
        float ui = ov[2 + i];
        float ct = coup * (pc[i] - ui * rho);
        ns[i] = jac[2 + i][3] + conv - visc * lap[2 + i] - ct;
    }
    float divg  = jac[2][0] + jac[3][1] + jac[4][2];
    float phase = atan2f(pim, pr);

    if (cmode == 2) {
        out[gw] = pr;
        out[Bn + gw * 3 + 0] = u0;
        out[Bn + gw * 3 + 1] = u1;
        out[Bn + gw * 3 + 2] = u2;
        out[4 * Bn + gw] = qr;
        out[5 * Bn + gw * 3 + 0] = ns[0];
        out[5 * Bn + gw * 3 + 1] = ns[1];
        out[5 * Bn + gw * 3 + 2] = ns[2];
        out[8 * Bn + gw]  = divg;
        out[9 * Bn + gw]  = rho;
        out[10 * Bn + gw] = phase;
        out[11 * Bn + gw * 3 + 0] = pc[0];
        out[11 * Bn + gw * 3 + 1] = pc[1];
        out[11 * Bn + gw * 3 + 2] = pc[2];
    } else if (cmode == 1) {
        float2* o2 = (float2*)out;
        o2[gw] = make_float2(pr, pim);
        o2[Bn + gw * 3 + 0] = make_float2(u0, 0.f);
        o2[Bn + gw * 3 + 1] = make_float2(u1, 0.f);
        o2[Bn + gw * 3 + 2] = make_float2(u2, 0.f);
        o2[4 * Bn + gw] = make_float2(qr, qi);
        o2[5 * Bn + gw * 3 + 0] = make_float2(ns[0], 0.f);
        o2[5 * Bn + gw * 3 + 1] = make_float2(ns[1], 0.f);
        o2[5 * Bn + gw * 3 + 2] = make_float2(ns[2], 0.f);
        o2[8 * Bn + gw]  = make_float2(divg, 0.f);
        o2[9 * Bn + gw]  = make_float2(rho, 0.f);
        o2[10 * Bn + gw] = make_float2(phase, 0.f);
        o2[11 * Bn + gw * 3 + 0] = make_float2(pc[0], 0.f);
        o2[11 * Bn + gw * 3 + 1] = make_float2(pc[1], 0.f);
        o2[11 * Bn + gw * 3 + 2] = make_float2(pc[2], 0.f);
    } else {
        out[2 * gw + 0] = pr;
        out[2 * gw + 1] = pim;
        out[2 * Bn + gw * 3 + 0] = u0;
        out[2 * Bn + gw * 3 + 1] = u1;
        out[2 * Bn + gw * 3 + 2] = u2;
        out[5 * Bn + 2 * gw + 0] = qr;
        out[5 * Bn + 2 * gw + 1] = qi;
        out[7 * Bn + gw * 3 + 0] = ns[0];
        out[7 * Bn + gw * 3 + 1] = ns[1];
        out[7 * Bn + gw * 3 + 2] = ns[2];
        out[10 * Bn + gw] = divg;
        out[11 * Bn + gw] = rho;
        out[12 * Bn + gw] = phase;
        out[13 * Bn + gw * 3 + 0] = pc[0];
        out[13 * Bn + gw * 3 + 1] = pc[1];
        out[13 * Bn + gw * 3 + 2] = pc[2];
    }
}

// ---------------------------------------------------------------------------
extern "C" void kernel_launch(void* const* d_in, const int* in_sizes, int n_in,
                              void* d_out, int out_size)
{
    const float *x = 0, *W0 = 0, *b0 = 0, *Wh = 0, *bh = 0, *Wo = 0, *bo = 0;
    const float* scal[3] = {0, 0, 0};
    int ns = 0;
    int Bn = 0;

    for (int i = 0; i < n_in; i++) {
        const float* p = (const float*)d_in[i];
        switch (in_sizes[i]) {
            case 8192 * 4:        x  = p; Bn = in_sizes[i] / 4; break;
            case 4 * 512:         W0 = p; break;
            case 512:             b0 = p; break;
            case 6 * 512 * 512:   Wh = p; break;
            case 6 * 512:         bh = p; break;
            case 512 * 5:         Wo = p; break;
            case 5:               bo = p; break;
            case 1:  if (ns < 3) scal[ns++] = p; break;
            default: break;
        }
    }
    if (!x || !W0 || !b0 || !Wh || !bh || !Wo || !bo || ns < 3) {
        x  = (const float*)d_in[0];  W0 = (const float*)d_in[1];
        b0 = (const float*)d_in[2];  Wh = (const float*)d_in[3];
        bh = (const float*)d_in[4];  Wo = (const float*)d_in[5];
        bo = (const float*)d_in[6];
        scal[0] = (const float*)d_in[7];
        scal[1] = (const float*)d_in[8];
        scal[2] = (const float*)d_in[9];
        Bn = in_sizes[0] / 4;
    }
    if (Bn <= 0 || Bn > MAXB) Bn = MAXB;

    __nv_bfloat16 *Ahi, *Alo, *Wth, *Wtl;
    cudaGetSymbolAddress((void**)&Ahi, g_Ahi);
    cudaGetSymbolAddress((void**)&Alo, g_Alo);
    cudaGetSymbolAddress((void**)&Wth, g_Wth);
    cudaGetSymbolAddress((void**)&Wtl, g_Wtl);

    cudaFuncSetAttribute(layer_mma_kernel,
                         cudaFuncAttributeMaxDynamicSharedMemorySize,
                         SMEM_TOTAL);

    prep_w_kernel<<<(6 * HDIM * HDIM + 255) / 256, 256>>>(Wh, Wth, Wtl);
    init_kernel<<<(Bn * HDIM + 255) / 256, 256>>>(x, W0, b0, Ahi, Alo, Bn);

    dim3 grid(HDIM / TN, (Bn * NVEC) / TM);
    int cur = 0;
    for (int l = 0; l < 6; l++) {
        int nxt = cur ^ 1;
        layer_mma_kernel<<<grid, 256, SMEM_TOTAL>>>(
            Ahi + (size_t)cur * PLANE, Alo + (size_t)cur * PLANE,
            Wth + (size_t)l * HDIM * HDIM, Wtl + (size_t)l * HDIM * HDIM,
            bh + (size_t)l * HDIM,
            Ahi + (size_t)nxt * PLANE, Alo + (size_t)nxt * PLANE);
        cur = nxt;
    }

    int cmode;
    if      (out_size == 14 * Bn) cmode = 2;
    else if (out_size == 16 * Bn) cmode = 0;
    else if (out_size == 28 * Bn) cmode = 1;
    else                          cmode = 2;

    final_kernel<<<(Bn + 7) / 8, 256>>>(Ahi + (size_t)cur * PLANE,
                                        Alo + (size_t)cur * PLANE,
                                        Wo, bo, scal[0], scal[1], scal[2],
                                        (float*)d_out, Bn, cmode);
}